// round 2
// baseline (speedup 1.0000x reference)
#include <cuda_runtime.h>

#define TPB   256
#define PTILE 16
#define PITCH 264      // 256 + 8 pad (keeps float4 alignment, breaks worst bank patterns)
#define HDIM  256
#define DIN   16
#define DOUT  128
#define BMAX  4096
#define NMAX  1100000

// Scratch (no allocations allowed)
__device__ long long d_offs[BMAX + 1];
__device__ int       d_seg[NMAX];
__device__ float     d_sums[BMAX * DOUT];
__device__ float     d_emb[BMAX * DOUT];

__device__ __forceinline__ long long get_count(const void* np, int i, int is64) {
    if (is64) return ((const long long*)np)[i];
    return (long long)((const int*)np)[i];
}

// Prefix-sum of num_points -> d_offs. Detects int32 vs int64 storage at runtime
// (int64 little-endian: odd 32-bit words are 0 since counts < 2^31; counts are >0).
__global__ void scan_offsets(const void* __restrict__ np, int Bn) {
    __shared__ long long part[256];
    __shared__ int s_is64;
    if (threadIdx.x == 0) {
        const int* p32 = (const int*)np;
        int is64 = 1;
        for (int i = 1; i < 7 && i < 2 * Bn; i += 2)
            if (p32[i] != 0) is64 = 0;
        s_is64 = is64;
    }
    __syncthreads();
    const int is64 = s_is64;
    const int chunk = (Bn + 255) / 256;
    const int c0 = threadIdx.x * chunk;
    long long s = 0;
    for (int i = 0; i < chunk; i++) {
        int idx = c0 + i;
        if (idx < Bn) s += get_count(np, idx, is64);
    }
    part[threadIdx.x] = s;
    __syncthreads();
    if (threadIdx.x == 0) {
        long long r = 0;
        for (int i = 0; i < 256; i++) { long long t = part[i]; part[i] = r; r += t; }
    }
    __syncthreads();
    long long base = part[threadIdx.x];
    for (int i = 0; i < chunk; i++) {
        int idx = c0 + i;
        if (idx < Bn) {
            d_offs[idx] = base;
            base += get_count(np, idx, is64);
            if (idx == Bn - 1) d_offs[Bn] = base;
        }
    }
}

__global__ void fill_seg(int Bn) {
    int b = blockIdx.x;
    long long lo = d_offs[b], hi = d_offs[b + 1];
    for (long long i = lo + threadIdx.x; i < hi; i += blockDim.x)
        d_seg[i] = b;
}

__global__ void zero_sums(int n) {
    int i = blockIdx.x * blockDim.x + threadIdx.x;
    if (i < n) d_sums[i] = 0.f;
}

// Fused: Linear(16->256) -> LN -> ReLU -> Linear(256->256) -> LN -> ReLU
//        -> Linear(256->128) -> run-length segment accumulate (atomic).
// thread = feature j; tile = 16 points per CTA.
__global__ __launch_bounds__(TPB, 2)
void mlp_pool(const float* __restrict__ z,
              const float* __restrict__ W1, const float* __restrict__ b1,
              const float* __restrict__ g1, const float* __restrict__ be1,
              const float* __restrict__ W2, const float* __restrict__ b2,
              const float* __restrict__ g2, const float* __restrict__ be2,
              const float* __restrict__ W3, const float* __restrict__ b3,
              int Npts)
{
    __shared__ __align__(16) float zs[PTILE][DIN];
    __shared__ __align__(16) float bufA[PTILE * PITCH];
    __shared__ __align__(16) float bufB[PTILE * PITCH];
    __shared__ float s_m[PTILE], s_r[PTILE];
    __shared__ int   ssg[PTILE];

    const int tid = threadIdx.x;
    const int j = tid;
    const int p0 = blockIdx.x * PTILE;
    const int npts = min(PTILE, Npts - p0);
    if (npts <= 0) return;

    // Per-thread parameter cache
    float w1r[DIN];
    #pragma unroll
    for (int k = 0; k < DIN; k++) w1r[k] = W1[k * HDIM + j];
    const float b1r = b1[j], g1r = g1[j], be1r = be1[j];
    const float b2r = b2[j], g2r = g2[j], be2r = be2[j];
    const int f = j & (DOUT - 1);
    const int half = j >> 7;
    const float b3r = b3[f];

    // z tile (coalesced: 256 consecutive floats) + seg ids
    {
        int p = tid / DIN, k = tid % DIN;
        zs[p][k] = (tid < npts * DIN) ? z[(long long)p0 * DIN + tid] : 0.f;
        if (tid < PTILE) ssg[tid] = (tid < npts) ? d_seg[p0 + tid] : 0;
    }
    __syncthreads();

    float acc[PTILE];

    // ---- Layer 1 ----
    #pragma unroll
    for (int p = 0; p < PTILE; p++) {
        float a = b1r;
        const float4* z4 = reinterpret_cast<const float4*>(zs[p]);
        #pragma unroll
        for (int q = 0; q < 4; q++) {
            float4 v = z4[q];
            a += v.x * w1r[4*q] + v.y * w1r[4*q+1] + v.z * w1r[4*q+2] + v.w * w1r[4*q+3];
        }
        acc[p] = a;
        bufA[p * PITCH + j] = a;
    }
    __syncthreads();

    // ---- LN1 stats (16 threads per point) ----
    {
        int g = tid >> 4, l = tid & 15;
        float s = 0.f, q = 0.f;
        #pragma unroll
        for (int t = 0; t < 16; t++) {
            float x = bufA[g * PITCH + l + 16 * t];
            s += x; q += x * x;
        }
        #pragma unroll
        for (int o = 8; o; o >>= 1) {
            s += __shfl_xor_sync(0xffffffffu, s, o);
            q += __shfl_xor_sync(0xffffffffu, q, o);
        }
        if (l == 0) {
            float m = s * (1.f / HDIM);
            float v = q * (1.f / HDIM) - m * m;
            s_m[g] = m;
            s_r[g] = rsqrtf(v + 1e-5f);
        }
    }
    __syncthreads();

    // normalize + ReLU (pre-norm value still in regs)
    #pragma unroll
    for (int p = 0; p < PTILE; p++) {
        float y = (acc[p] - s_m[p]) * s_r[p] * g1r + be1r;
        bufA[p * PITCH + j] = fmaxf(y, 0.f);
    }
    __syncthreads();

    // ---- Layer 2 (256x256), W2 column j register-cached in k-chunks of 32 ----
    #pragma unroll
    for (int p = 0; p < PTILE; p++) acc[p] = b2r;
    for (int kc = 0; kc < HDIM; kc += 32) {
        float4 w4[8];
        #pragma unroll
        for (int i = 0; i < 8; i++) {
            int k = kc + 4 * i;
            w4[i] = make_float4(W2[(k + 0) * HDIM + j], W2[(k + 1) * HDIM + j],
                                W2[(k + 2) * HDIM + j], W2[(k + 3) * HDIM + j]);
        }
        #pragma unroll
        for (int i = 0; i < 8; i++) {
            #pragma unroll
            for (int p = 0; p < PTILE; p++) {
                const float4 h4 = *reinterpret_cast<const float4*>(&bufA[p * PITCH + kc + 4 * i]);
                acc[p] += h4.x * w4[i].x + h4.y * w4[i].y + h4.z * w4[i].z + h4.w * w4[i].w;
            }
        }
    }

    #pragma unroll
    for (int p = 0; p < PTILE; p++) bufB[p * PITCH + j] = acc[p];
    __syncthreads();

    // ---- LN2 stats ----
    {
        int g = tid >> 4, l = tid & 15;
        float s = 0.f, q = 0.f;
        #pragma unroll
        for (int t = 0; t < 16; t++) {
            float x = bufB[g * PITCH + l + 16 * t];
            s += x; q += x * x;
        }
        #pragma unroll
        for (int o = 8; o; o >>= 1) {
            s += __shfl_xor_sync(0xffffffffu, s, o);
            q += __shfl_xor_sync(0xffffffffu, q, o);
        }
        if (l == 0) {
            float m = s * (1.f / HDIM);
            float v = q * (1.f / HDIM) - m * m;
            s_m[g] = m;
            s_r[g] = rsqrtf(v + 1e-5f);
        }
    }
    __syncthreads();

    #pragma unroll
    for (int p = 0; p < PTILE; p++) {
        float y = (acc[p] - s_m[p]) * s_r[p] * g2r + be2r;
        bufB[p * PITCH + j] = fmaxf(y, 0.f);
    }
    __syncthreads();

    // ---- Layer 3 (256x128), split-k: threads 0..127 do k in [0,128), 128..255 do [128,256) ----
    float acc3[PTILE];
    #pragma unroll
    for (int p = 0; p < PTILE; p++) acc3[p] = (half == 0) ? b3r : 0.f;
    const int kbase = half * 128;
    for (int kc = 0; kc < 128; kc += 32) {
        float4 w4[8];
        #pragma unroll
        for (int i = 0; i < 8; i++) {
            int k = kbase + kc + 4 * i;
            w4[i] = make_float4(W3[(k + 0) * DOUT + f], W3[(k + 1) * DOUT + f],
                                W3[(k + 2) * DOUT + f], W3[(k + 3) * DOUT + f]);
        }
        #pragma unroll
        for (int i = 0; i < 8; i++) {
            #pragma unroll
            for (int p = 0; p < PTILE; p++) {
                const float4 h4 = *reinterpret_cast<const float4*>(&bufB[p * PITCH + kbase + kc + 4 * i]);
                acc3[p] += h4.x * w4[i].x + h4.y * w4[i].y + h4.z * w4[i].z + h4.w * w4[i].w;
            }
        }
    }

    // combine split-k halves via bufA (free now)
    if (half) {
        #pragma unroll
        for (int p = 0; p < PTILE; p++) bufA[p * PITCH + f] = acc3[p];
    }
    __syncthreads();

    if (!half) {
        // run-length segment accumulation (tiles are contiguous points -> few runs)
        float run = 0.f;
        int cur = ssg[0];
        for (int p = 0; p < npts; p++) {
            float phi = acc3[p] + bufA[p * PITCH + f];
            int sp = ssg[p];
            if (sp != cur) {
                atomicAdd(&d_sums[cur * DOUT + f], run);
                run = 0.f;
                cur = sp;
            }
            run += phi;
        }
        atomicAdd(&d_sums[cur * DOUT + f], run);
    }
}

__global__ void finalize_means(int Bn) {
    int i = blockIdx.x * blockDim.x + threadIdx.x;
    if (i < Bn * DOUT) {
        int b = i >> 7;
        float cnt = (float)(d_offs[b + 1] - d_offs[b]);
        d_emb[i] = d_sums[i] / cnt;
    }
}

__global__ void broadcast_out(float4* __restrict__ out, long long total4) {
    long long i = (long long)blockIdx.x * blockDim.x + threadIdx.x;
    if (i < total4) {
        long long p = i >> 5;            // point index
        int c = (int)(i & 31);           // float4 column within 128 floats
        const float4* emb4 = reinterpret_cast<const float4*>(d_emb);
        out[i] = emb4[(long long)d_seg[p] * 32 + c];
    }
}

extern "C" void kernel_launch(void* const* d_in, const int* in_sizes, int n_in,
                              void* d_out, int out_size) {
    const float* z   = (const float*)d_in[0];
    const float* W1  = (const float*)d_in[1];
    const float* b1  = (const float*)d_in[2];
    const float* g1  = (const float*)d_in[3];
    const float* be1 = (const float*)d_in[4];
    const float* W2  = (const float*)d_in[5];
    const float* b2  = (const float*)d_in[6];
    const float* g2  = (const float*)d_in[7];
    const float* be2 = (const float*)d_in[8];
    const float* W3  = (const float*)d_in[9];
    const float* b3  = (const float*)d_in[10];
    const void*  np  = d_in[11];

    const int Bn = in_sizes[11];
    const int N  = in_sizes[0] / DIN;

    scan_offsets<<<1, 256>>>(np, Bn);
    fill_seg<<<Bn, 128>>>(Bn);
    zero_sums<<<(Bn * DOUT + 255) / 256, 256>>>(Bn * DOUT);

    const int tiles = (N + PTILE - 1) / PTILE;
    mlp_pool<<<tiles, TPB>>>(z, W1, b1, g1, be1, W2, b2, g2, be2, W3, b3, N);

    finalize_means<<<(Bn * DOUT + 255) / 256, 256>>>(Bn);

    const long long total4 = (long long)N * (DOUT / 4);
    const int bl = (int)((total4 + 255) / 256);
    broadcast_out<<<bl, 256>>>((float4*)d_out, total4);
}

// round 3
// speedup vs baseline: 3.7629x; 3.7629x over previous
#include <cuda_runtime.h>

#define TPB    256
#define MT     64          // points per CTA
#define HDIM   256
#define DIN    16
#define DOUT   128
#define PITCH  260         // floats; (PITCH*g + tg) % 32 distinct for g<8,tg<4 -> conflict-free A loads
#define ZPITCH 20          // same property for the z tile
#define BMAX   4096
#define NMAX   1100000

// ---------------- device scratch (no allocations allowed) ----------------
__device__ long long d_offs[BMAX + 1];
__device__ int       d_seg[NMAX];
__device__ float     d_sums[BMAX * DOUT];
__device__ float     d_emb[BMAX * DOUT];
__device__ float     d_W1t[DIN * HDIM];
__device__ float     d_W2t[HDIM * HDIM];
__device__ float     d_W3t[HDIM * DOUT];

// ---------------- helpers ----------------
__device__ __forceinline__ float to_tf32(float x) {
    float r; asm("cvt.rna.tf32.f32 %0, %1;" : "=f"(r) : "f"(x)); return r;
}

__device__ __forceinline__ void mma_tf32(float4& d,
                                         unsigned a0, unsigned a1, unsigned a2, unsigned a3,
                                         unsigned b0, unsigned b1) {
    asm volatile(
        "mma.sync.aligned.m16n8k8.row.col.f32.tf32.tf32.f32 "
        "{%0,%1,%2,%3}, {%4,%5,%6,%7}, {%8,%9}, {%0,%1,%2,%3};"
        : "+f"(d.x), "+f"(d.y), "+f"(d.z), "+f"(d.w)
        : "r"(a0), "r"(a1), "r"(a2), "r"(a3), "r"(b0), "r"(b1));
}

__device__ __forceinline__ long long get_count(const void* np, int i, int is64) {
    if (is64) return ((const long long*)np)[i];
    return (long long)((const int*)np)[i];
}

// ---------------- small setup kernels ----------------
__global__ void scan_offsets(const void* __restrict__ np, int Bn) {
    __shared__ long long part[256];
    __shared__ int s_is64;
    if (threadIdx.x == 0) {
        const int* p32 = (const int*)np;
        int is64 = 1;
        for (int i = 1; i < 7 && i < 2 * Bn; i += 2)
            if (p32[i] != 0) is64 = 0;
        s_is64 = is64;
    }
    __syncthreads();
    const int is64 = s_is64;
    const int chunk = (Bn + 255) / 256;
    const int c0 = threadIdx.x * chunk;
    long long s = 0;
    for (int i = 0; i < chunk; i++) {
        int idx = c0 + i;
        if (idx < Bn) s += get_count(np, idx, is64);
    }
    part[threadIdx.x] = s;
    __syncthreads();
    if (threadIdx.x == 0) {
        long long r = 0;
        for (int i = 0; i < 256; i++) { long long t = part[i]; part[i] = r; r += t; }
    }
    __syncthreads();
    long long base = part[threadIdx.x];
    for (int i = 0; i < chunk; i++) {
        int idx = c0 + i;
        if (idx < Bn) {
            d_offs[idx] = base;
            base += get_count(np, idx, is64);
            if (idx == Bn - 1) d_offs[Bn] = base;
        }
    }
}

__global__ void fill_seg(int Bn) {
    int b = blockIdx.x;
    long long lo = d_offs[b], hi = d_offs[b + 1];
    for (long long i = lo + threadIdx.x; i < hi; i += blockDim.x)
        d_seg[i] = b;
}

__global__ void zero_sums(int n) {
    int i = blockIdx.x * blockDim.x + threadIdx.x;
    if (i < n) d_sums[i] = 0.f;
}

__global__ void cvt_weights(const float* __restrict__ W1,
                            const float* __restrict__ W2,
                            const float* __restrict__ W3) {
    int i = blockIdx.x * 256 + threadIdx.x;
    if (i < DIN * HDIM)  d_W1t[i] = to_tf32(W1[i]);
    if (i < HDIM * HDIM) d_W2t[i] = to_tf32(W2[i]);
    if (i < HDIM * DOUT) d_W3t[i] = to_tf32(W3[i]);
}

// ---------------- LN + ReLU over sbuf [64][PITCH], 256 cols valid ----------------
// bias added pre-stats (it shifts mean/var). Output stored tf32-truncated + ReLU.
__device__ __forceinline__ void ln_relu(float* sbuf, const float* bi, const float* ga,
                                        const float* be, int tid) {
    const int p = tid >> 2, l = tid & 3;
    float* row = sbuf + p * PITCH;
    float s = 0.f, q = 0.f;
    #pragma unroll
    for (int i = 0; i < 16; i++) {
        int c = 4 * (l + 4 * i);
        float4 x = *(const float4*)(row + c);
        float4 bb = *(const float4*)(bi + c);
        x.x += bb.x; x.y += bb.y; x.z += bb.z; x.w += bb.w;
        s += x.x + x.y + x.z + x.w;
        q += x.x * x.x + x.y * x.y + x.z * x.z + x.w * x.w;
    }
    s += __shfl_xor_sync(0xffffffffu, s, 1);
    q += __shfl_xor_sync(0xffffffffu, q, 1);
    s += __shfl_xor_sync(0xffffffffu, s, 2);
    q += __shfl_xor_sync(0xffffffffu, q, 2);
    const float m = s * (1.f / 256.f);
    const float r = rsqrtf(q * (1.f / 256.f) - m * m + 1e-5f);
    #pragma unroll
    for (int i = 0; i < 16; i++) {
        int c = 4 * (l + 4 * i);
        float4 x  = *(const float4*)(row + c);
        float4 bb = *(const float4*)(bi + c);
        float4 gg = *(const float4*)(ga + c);
        float4 ee = *(const float4*)(be + c);
        float4 y;
        y.x = to_tf32(fmaxf((x.x + bb.x - m) * r * gg.x + ee.x, 0.f));
        y.y = to_tf32(fmaxf((x.y + bb.y - m) * r * gg.y + ee.y, 0.f));
        y.z = to_tf32(fmaxf((x.z + bb.z - m) * r * gg.z + ee.z, 0.f));
        y.w = to_tf32(fmaxf((x.w + bb.w - m) * r * gg.w + ee.w, 0.f));
        *(float4*)(row + c) = y;
    }
}

// ---------------- main fused kernel: 3-layer MLP on tensor pipe + segment pool ----------------
__global__ __launch_bounds__(TPB, 2)
void mlp_mma(const float* __restrict__ z,
             const float* __restrict__ b1, const float* __restrict__ g1, const float* __restrict__ be1,
             const float* __restrict__ b2, const float* __restrict__ g2, const float* __restrict__ be2,
             const float* __restrict__ b3,
             int Npts)
{
    extern __shared__ char smem_raw[];
    float* sbuf = (float*)smem_raw;                 // 64*PITCH
    float* zs   = sbuf + MT * PITCH;                // 64*ZPITCH
    float* sb1  = zs + MT * ZPITCH;
    float* sg1  = sb1 + HDIM;
    float* sbe1 = sg1 + HDIM;
    float* sb2  = sbe1 + HDIM;
    float* sg2  = sb2 + HDIM;
    float* sbe2 = sg2 + HDIM;
    float* sb3  = sbe2 + HDIM;                      // 128
    int*   ssg  = (int*)(sb3 + DOUT);               // 64

    const int tid = threadIdx.x;
    const int p0 = blockIdx.x * MT;
    const int npts = min(MT, Npts - p0);
    if (npts <= 0) return;

    // ---- load z tile (tf32-truncated), params, seg ids ----
    {
        const float4* z4 = (const float4*)(z + (long long)p0 * DIN);
        int pi = tid >> 2, ci = tid & 3;            // point, float4 chunk (4 chunks of 4 = 16)
        float4 v = make_float4(0.f, 0.f, 0.f, 0.f);
        if (pi < npts) v = z4[pi * 4 + ci];
        float* zr = zs + pi * ZPITCH + 4 * ci;
        zr[0] = to_tf32(v.x); zr[1] = to_tf32(v.y); zr[2] = to_tf32(v.z); zr[3] = to_tf32(v.w);

        sb1[tid] = b1[tid]; sg1[tid] = g1[tid]; sbe1[tid] = be1[tid];
        sb2[tid] = b2[tid]; sg2[tid] = g2[tid]; sbe2[tid] = be2[tid];
        if (tid < DOUT) sb3[tid] = b3[tid];
        if (tid < MT) ssg[tid] = (tid < npts) ? d_seg[p0 + tid] : 0;
    }
    __syncthreads();

    const int warp = tid >> 5, lane = tid & 31;
    const int g = lane >> 2, tg = lane & 3;
    const int n0 = warp * 32;                       // 32-col slice for H=256 layers

    // ================= Layer 1: [64x16] @ [16x256] =================
    {
        float4 acc[4][4];
        #pragma unroll
        for (int m = 0; m < 4; m++)
            #pragma unroll
            for (int t = 0; t < 4; t++) acc[m][t] = make_float4(0.f, 0.f, 0.f, 0.f);

        #pragma unroll
        for (int ks = 0; ks < 2; ks++) {
            const int k = 8 * ks;
            unsigned a[4][4];
            #pragma unroll
            for (int m = 0; m < 4; m++) {
                const float* ar = zs + (16 * m + g) * ZPITCH + k + tg;
                a[m][0] = __float_as_uint(ar[0]);
                a[m][1] = __float_as_uint(ar[8 * ZPITCH]);
                a[m][2] = __float_as_uint(ar[4]);
                a[m][3] = __float_as_uint(ar[8 * ZPITCH + 4]);
            }
            #pragma unroll
            for (int t = 0; t < 4; t++) {
                const int n = n0 + 8 * t;
                unsigned w0 = __float_as_uint(d_W1t[(k + tg) * HDIM + n + g]);
                unsigned w1 = __float_as_uint(d_W1t[(k + tg + 4) * HDIM + n + g]);
                #pragma unroll
                for (int m = 0; m < 4; m++)
                    mma_tf32(acc[m][t], a[m][0], a[m][1], a[m][2], a[m][3], w0, w1);
            }
        }
        #pragma unroll
        for (int m = 0; m < 4; m++)
            #pragma unroll
            for (int t = 0; t < 4; t++) {
                float* cr = sbuf + (16 * m + g) * PITCH + n0 + 8 * t + 2 * tg;
                cr[0] = acc[m][t].x; cr[1] = acc[m][t].y;
                cr[8 * PITCH] = acc[m][t].z; cr[8 * PITCH + 1] = acc[m][t].w;
            }
    }
    __syncthreads();
    ln_relu(sbuf, sb1, sg1, sbe1, tid);
    __syncthreads();

    // ================= Layer 2: [64x256] @ [256x256] =================
    {
        float4 acc[4][4];
        #pragma unroll
        for (int m = 0; m < 4; m++)
            #pragma unroll
            for (int t = 0; t < 4; t++) acc[m][t] = make_float4(0.f, 0.f, 0.f, 0.f);

        for (int ks = 0; ks < 32; ks++) {
            const int k = 8 * ks;
            unsigned a[4][4];
            #pragma unroll
            for (int m = 0; m < 4; m++) {
                const float* ar = sbuf + (16 * m + g) * PITCH + k + tg;
                a[m][0] = __float_as_uint(ar[0]);
                a[m][1] = __float_as_uint(ar[8 * PITCH]);
                a[m][2] = __float_as_uint(ar[4]);
                a[m][3] = __float_as_uint(ar[8 * PITCH + 4]);
            }
            unsigned bw[4][2];
            #pragma unroll
            for (int t = 0; t < 4; t++) {
                const int n = n0 + 8 * t;
                bw[t][0] = __float_as_uint(d_W2t[(k + tg) * HDIM + n + g]);
                bw[t][1] = __float_as_uint(d_W2t[(k + tg + 4) * HDIM + n + g]);
            }
            #pragma unroll
            for (int t = 0; t < 4; t++)
                #pragma unroll
                for (int m = 0; m < 4; m++)
                    mma_tf32(acc[m][t], a[m][0], a[m][1], a[m][2], a[m][3], bw[t][0], bw[t][1]);
        }
        __syncthreads();   // all A reads done before overwriting sbuf
        #pragma unroll
        for (int m = 0; m < 4; m++)
            #pragma unroll
            for (int t = 0; t < 4; t++) {
                float* cr = sbuf + (16 * m + g) * PITCH + n0 + 8 * t + 2 * tg;
                cr[0] = acc[m][t].x; cr[1] = acc[m][t].y;
                cr[8 * PITCH] = acc[m][t].z; cr[8 * PITCH + 1] = acc[m][t].w;
            }
    }
    __syncthreads();
    ln_relu(sbuf, sb2, sg2, sbe2, tid);
    __syncthreads();

    // ================= Layer 3: [64x256] @ [256x128] =================
    {
        const int n3 = warp * 16;                   // 16-col slice for DOUT=128
        float4 acc[4][2];
        #pragma unroll
        for (int m = 0; m < 4; m++)
            #pragma unroll
            for (int t = 0; t < 2; t++) acc[m][t] = make_float4(0.f, 0.f, 0.f, 0.f);

        for (int ks = 0; ks < 32; ks++) {
            const int k = 8 * ks;
            unsigned a[4][4];
            #pragma unroll
            for (int m = 0; m < 4; m++) {
                const float* ar = sbuf + (16 * m + g) * PITCH + k + tg;
                a[m][0] = __float_as_uint(ar[0]);
                a[m][1] = __float_as_uint(ar[8 * PITCH]);
                a[m][2] = __float_as_uint(ar[4]);
                a[m][3] = __float_as_uint(ar[8 * PITCH + 4]);
            }
            #pragma unroll
            for (int t = 0; t < 2; t++) {
                const int n = n3 + 8 * t;
                unsigned w0 = __float_as_uint(d_W3t[(k + tg) * DOUT + n + g]);
                unsigned w1 = __float_as_uint(d_W3t[(k + tg + 4) * DOUT + n + g]);
                #pragma unroll
                for (int m = 0; m < 4; m++)
                    mma_tf32(acc[m][t], a[m][0], a[m][1], a[m][2], a[m][3], w0, w1);
            }
        }
        __syncthreads();
        #pragma unroll
        for (int m = 0; m < 4; m++)
            #pragma unroll
            for (int t = 0; t < 2; t++) {
                float* cr = sbuf + (16 * m + g) * PITCH + n3 + 8 * t + 2 * tg;
                cr[0] = acc[m][t].x; cr[1] = acc[m][t].y;
                cr[8 * PITCH] = acc[m][t].z; cr[8 * PITCH + 1] = acc[m][t].w;
            }
    }
    __syncthreads();

    // ================= epilogue: bias + run-length segment accumulate =================
    {
        const int f = tid & (DOUT - 1);
        const int half = tid >> 7;
        const int ps = half * 32;
        const int pe = min(ps + 32, npts);
        if (ps < pe) {
            const float bf = sb3[f];
            int cur = ssg[ps];
            float run = 0.f;
            for (int p = ps; p < pe; p++) {
                float phi = sbuf[p * PITCH + f] + bf;
                int sp = ssg[p];
                if (sp != cur) {
                    atomicAdd(&d_sums[cur * DOUT + f], run);
                    run = 0.f;
                    cur = sp;
                }
                run += phi;
            }
            atomicAdd(&d_sums[cur * DOUT + f], run);
        }
    }
}

__global__ void finalize_means(int Bn) {
    int i = blockIdx.x * blockDim.x + threadIdx.x;
    if (i < Bn * DOUT) {
        int b = i >> 7;
        float cnt = (float)(d_offs[b + 1] - d_offs[b]);
        d_emb[i] = d_sums[i] / cnt;
    }
}

__global__ void broadcast_out(float4* __restrict__ out, long long total4) {
    long long i = (long long)blockIdx.x * blockDim.x + threadIdx.x;
    if (i < total4) {
        long long p = i >> 5;
        int c = (int)(i & 31);
        const float4* emb4 = reinterpret_cast<const float4*>(d_emb);
        out[i] = emb4[(long long)d_seg[p] * 32 + c];
    }
}

extern "C" void kernel_launch(void* const* d_in, const int* in_sizes, int n_in,
                              void* d_out, int out_size) {
    const float* z   = (const float*)d_in[0];
    const float* W1  = (const float*)d_in[1];
    const float* b1  = (const float*)d_in[2];
    const float* g1  = (const float*)d_in[3];
    const float* be1 = (const float*)d_in[4];
    const float* W2  = (const float*)d_in[5];
    const float* b2  = (const float*)d_in[6];
    const float* g2  = (const float*)d_in[7];
    const float* be2 = (const float*)d_in[8];
    const float* W3  = (const float*)d_in[9];
    const float* b3  = (const float*)d_in[10];
    const void*  np  = d_in[11];

    const int Bn = in_sizes[11];
    const int N  = in_sizes[0] / DIN;

    static const size_t SMEM_BYTES =
        (MT * PITCH + MT * ZPITCH + 6 * HDIM + DOUT) * sizeof(float) + MT * sizeof(int);
    cudaFuncSetAttribute(mlp_mma, cudaFuncAttributeMaxDynamicSharedMemorySize,
                         (int)SMEM_BYTES);

    scan_offsets<<<1, 256>>>(np, Bn);
    fill_seg<<<Bn, 128>>>(Bn);
    zero_sums<<<(Bn * DOUT + 255) / 256, 256>>>(Bn * DOUT);
    cvt_weights<<<256, 256>>>(W1, W2, W3);

    const int tiles = (N + MT - 1) / MT;
    mlp_mma<<<tiles, TPB, SMEM_BYTES>>>(z, b1, g1, be1, b2, g2, be2, b3, N);

    finalize_means<<<(Bn * DOUT + 255) / 256, 256>>>(Bn);

    const long long total4 = (long long)N * (DOUT / 4);
    broadcast_out<<<(int)((total4 + 255) / 256), 256>>>((float4*)d_out, total4);
}